// round 11
// baseline (speedup 1.0000x reference)
#include <cuda_runtime.h>
#include <cuda_bf16.h>
#include <math.h>
#include <stdint.h>

#define NN 4096
#define F_IN 128
#define F_OUT 64
#define HH 4
#define NEG_INF -1e9f
#define LN_EPS 1e-5f
#define NTILE 64
#define LOG2E 1.4426950408889634f

// ---------------- scratch (device globals: allocation-free) ----------------
__device__ float g_mask[(size_t)NN * NN];                      // 64 MB
__device__ __align__(16) __nv_bfloat16 g_projp[HH][NTILE][64][72];
__device__ float g_skip[NN * HH * F_OUT];
__device__ float g_ssrc[HH * NN];                              // raw
__device__ float g_stgt[HH * NN];                              // raw (for k2)
__device__ __align__(16) float g_stgt2[NTILE][HH][64];         // x log2e (for k3)
__device__ float g_part[32 * HH * NN];
__device__ __align__(16) float g_nld2[NTILE][HH][64];          // -log2(denom)
__device__ float g_pout[8][NN * HH * F_OUT];                   // j-split partials

// ---------------- asm helpers ----------------------------------------------
__device__ __forceinline__ uint32_t smem_u32(const void* p) {
    return (uint32_t)__cvta_generic_to_shared(p);
}
__device__ __forceinline__ void bulkcp(void* s, const void* g, int bytes,
                                       uint32_t mbar) {
    asm volatile(
        "cp.async.bulk.shared::cta.global.mbarrier::complete_tx::bytes "
        "[%0], [%1], %2, [%3];"
        :: "r"(smem_u32(s)), "l"(g), "r"(bytes), "r"(mbar) : "memory");
}
__device__ __forceinline__ void mbar_init(uint32_t mbar, uint32_t cnt) {
    asm volatile("mbarrier.init.shared.b64 [%0], %1;" :: "r"(mbar), "r"(cnt) : "memory");
}
__device__ __forceinline__ void mbar_expect_tx(uint32_t mbar, uint32_t bytes) {
    asm volatile("mbarrier.arrive.expect_tx.shared.b64 _, [%0], %1;"
                 :: "r"(mbar), "r"(bytes) : "memory");
}
__device__ __forceinline__ void mbar_arrive(uint32_t mbar) {
    asm volatile("mbarrier.arrive.release.cta.shared::cta.b64 _, [%0];"
                 :: "r"(mbar) : "memory");
}
__device__ __forceinline__ void mbar_wait(uint32_t mbar, uint32_t parity) {
    asm volatile(
        "{\n\t.reg .pred P1;\n\t"
        "WAIT_LOOP_%=:\n\t"
        "mbarrier.try_wait.parity.acquire.cta.shared::cta.b64 P1, [%0], %1, 0x989680;\n\t"
        "@P1 bra.uni WAIT_DONE_%=;\n\t"
        "bra.uni WAIT_LOOP_%=;\n\t"
        "WAIT_DONE_%=:\n\t}"
        :: "r"(mbar), "r"(parity) : "memory");
}
__device__ __forceinline__ float ex2f(float x) {
    float r;
    asm("ex2.approx.ftz.f32 %0, %1;" : "=f"(r) : "f"(x));
    return r;
}
__device__ __forceinline__ uint32_t packbf2(float lo, float hi) {
    __nv_bfloat162 v = __floats2bfloat162_rn(lo, hi);
    return *(uint32_t*)&v;
}

#define LDSM_X4T(r0, r1, r2, r3, a) \
    asm volatile("ldmatrix.sync.aligned.m8n8.x4.trans.shared.b16 {%0,%1,%2,%3}, [%4];" \
                 : "=r"(r0), "=r"(r1), "=r"(r2), "=r"(r3) : "r"(a))

__device__ __forceinline__ void mma_bf16(float* c, uint32_t a0, uint32_t a1,
                                         uint32_t a2, uint32_t a3,
                                         uint32_t b0, uint32_t b1) {
    asm volatile(
        "mma.sync.aligned.m16n8k16.row.col.f32.bf16.bf16.f32 "
        "{%0,%1,%2,%3}, {%4,%5,%6,%7}, {%8,%9}, {%0,%1,%2,%3};"
        : "+f"(c[0]), "+f"(c[1]), "+f"(c[2]), "+f"(c[3])
        : "r"(a0), "r"(a1), "r"(a2), "r"(a3), "r"(b0), "r"(b1));
}

// ---------------- k0: fused proj(bf16) + scores + skip ---------------------
__global__ void k0_fused(const float* __restrict__ nodes,
                         const float* __restrict__ pp,
                         const float* __restrict__ skw,
                         const float* __restrict__ wsrc,
                         const float* __restrict__ wtgt) {
    __shared__ float xs[16][F_IN];
    __shared__ float red[2][2][HH][16];
    const int nbase = blockIdx.x * 16;
    const int tid = threadIdx.x;
    for (int q = tid; q < 16 * F_IN; q += 256)
        xs[q >> 7][q & 127] = nodes[nbase * F_IN + q];
    __syncthreads();

    const int h = tid >> 6, o = tid & 63;
    const int lane = tid & 31, half = (tid >> 5) & 1;
    const int jt = nbase >> 6, rbase = nbase & 63;

    float acc[16];
#pragma unroll
    for (int k = 0; k < 16; k++) acc[k] = 0.f;
    for (int f = 0; f < F_IN; f++) {
        float w = pp[h * F_IN * F_OUT + f * F_OUT + o];
#pragma unroll
        for (int k = 0; k < 16; k++) acc[k] += xs[k][f] * w;
    }
#pragma unroll
    for (int k = 0; k < 16; k++)
        g_projp[h][jt][rbase + k][o] = __float2bfloat16_rn(acc[k]);

    {
        const float ws = wsrc[h * F_OUT + o];
        const float wt = wtgt[h * F_OUT + o];
#pragma unroll
        for (int k = 0; k < 16; k++) {
            float s = acc[k] * ws, t = acc[k] * wt;
#pragma unroll
            for (int off = 16; off; off >>= 1) {
                s += __shfl_down_sync(0xffffffffu, s, off);
                t += __shfl_down_sync(0xffffffffu, t, off);
            }
            if (lane == 0) { red[0][half][h][k] = s; red[1][half][h][k] = t; }
        }
    }
    __syncthreads();
    if (tid < 128) {
        const int h2 = tid >> 5, k = (tid >> 1) & 15, sel = tid & 1;
        const float v = red[sel][0][h2][k] + red[sel][1][h2][k];
        const int n = nbase + k;
        if (sel == 0) g_ssrc[h2 * NN + n] = v;
        else {
            g_stgt[h2 * NN + n] = v;
            g_stgt2[n >> 6][h2][n & 63] = v * LOG2E;
        }
    }

#pragma unroll
    for (int k = 0; k < 16; k++) acc[k] = 0.f;
    for (int f = 0; f < F_IN; f++) {
        float w = skw[tid * F_IN + f];
#pragma unroll
        for (int k = 0; k < 16; k++) acc[k] += xs[k][f] * w;
    }
#pragma unroll
    for (int k = 0; k < 16; k++)
        g_skip[(nbase + k) * (HH * F_OUT) + tid] = acc[k];
}

// ---------------- k1: mask + row LayerNorm (vectorized, streaming) ---------
__global__ void k1_mask_ln(const float* __restrict__ deg,
                           const float* __restrict__ bond,
                           const int* __restrict__ cutoff_p,
                           float* __restrict__ ln_out) {
    const int i = blockIdx.x;
    const int tid = threadIdx.x;
    const float cut = (float)(*cutoff_p);
    const size_t row = (size_t)i * NN;

    float4 m4[2];
    float s = 0.f, s2 = 0.f;
#pragma unroll
    for (int k = 0; k < 2; k++) {
        const int j4 = (k * 512 + tid) * 4;
        const float4 d4 = __ldcs((const float4*)&deg[row + j4]);
        const float4 b4 = __ldcs((const float4*)&bond[row + j4]);
        float4 m;
        float w;
        w = d4.x + b4.x; m.x = (w > 0.f) ? w : ((b4.x > cut) ? (b4.x + w) : NEG_INF);
        w = d4.y + b4.y; m.y = (w > 0.f) ? w : ((b4.y > cut) ? (b4.y + w) : NEG_INF);
        w = d4.z + b4.z; m.z = (w > 0.f) ? w : ((b4.z > cut) ? (b4.z + w) : NEG_INF);
        w = d4.w + b4.w; m.w = (w > 0.f) ? w : ((b4.w > cut) ? (b4.w + w) : NEG_INF);
        m4[k] = m;
        *(float4*)&g_mask[row + j4] = m;
        s  += (m.x + m.y) + (m.z + m.w);
        s2 += (m.x * m.x + m.y * m.y) + (m.z * m.z + m.w * m.w);
    }
    __shared__ float rs[16], rs2[16];
    const int lane = tid & 31, wp = tid >> 5;
#pragma unroll
    for (int off = 16; off; off >>= 1) {
        s  += __shfl_down_sync(0xffffffffu, s, off);
        s2 += __shfl_down_sync(0xffffffffu, s2, off);
    }
    if (lane == 0) { rs[wp] = s; rs2[wp] = s2; }
    __syncthreads();
    if (wp == 0) {
        float a  = (lane < 16) ? rs[lane] : 0.f;
        float a2 = (lane < 16) ? rs2[lane] : 0.f;
#pragma unroll
        for (int off = 8; off; off >>= 1) {
            a  += __shfl_down_sync(0xffffffffu, a, off);
            a2 += __shfl_down_sync(0xffffffffu, a2, off);
        }
        if (lane == 0) { rs[0] = a; rs2[0] = a2; }
    }
    __syncthreads();
    const float mu  = rs[0] * (1.0f / NN);
    const float var = fmaxf(rs2[0] * (1.0f / NN) - mu * mu, 0.f);
    const float rstd = 1.0f / sqrtf(var + LN_EPS);
#pragma unroll
    for (int k = 0; k < 2; k++) {
        const int j4 = (k * 512 + tid) * 4;
        float4 o4;
        o4.x = (m4[k].x - mu) * rstd;
        o4.y = (m4[k].y - mu) * rstd;
        o4.z = (m4[k].z - mu) * rstd;
        o4.w = (m4[k].w - mu) * rstd;
        __stcs((float4*)&ln_out[row + j4], o4);
    }
}

// ---------------- k2: column exp partial sums (reads mask) -----------------
__global__ void k2_colsum() {
    const int j = blockIdx.x * 256 + threadIdx.x;
    const int ibase = blockIdx.y * 128;
    __shared__ float ss[HH][128];
    for (int q = threadIdx.x; q < HH * 128; q += 256) {
        const int h = q >> 7, ii = q & 127;
        ss[h][ii] = g_ssrc[h * NN + ibase + ii];
    }
    __syncthreads();

    float st[HH], acc[HH];
#pragma unroll
    for (int h = 0; h < HH; h++) { st[h] = g_stgt[h * NN + j]; acc[h] = 0.f; }
    for (int ii = 0; ii < 128; ii += 4) {
        const size_t base = (size_t)(ibase + ii) * NN + j;
        float mrow[4];
        mrow[0] = g_mask[base];
        mrow[1] = g_mask[base + NN];
        mrow[2] = g_mask[base + 2 * NN];
        mrow[3] = g_mask[base + 3 * NN];
#pragma unroll
        for (int q = 0; q < 4; q++) {
#pragma unroll
            for (int h = 0; h < HH; h++) {
                float a = ss[h][ii + q] + st[h];
                a = fmaxf(a, 0.2f * a);
                acc[h] += __expf(a + mrow[q]);
            }
        }
    }
#pragma unroll
    for (int h = 0; h < HH; h++)
        g_part[(blockIdx.y * HH + h) * NN + j] = acc[h];
}

__global__ void k2b_reduce() {
    const int id = blockIdx.x * 256 + threadIdx.x;   // h*NN + j
    float s = 0.f;
#pragma unroll
    for (int c = 0; c < 32; c++) s += g_part[c * HH * NN + id];
    const int h = id >> 12, j = id & (NN - 1);
    g_nld2[j >> 6][h][j & 63] = -__log2f(s);
}

// ---------------- k3: 2-head blocks, 3 blocks/SM, bf16 mma -----------------
// grid (64, 8, 2): x = i-tile of 64, y = j-eighth (8 tiles), z = head pair.
// block 256 = 8 warps = 2 heads x 4 m-quarters (16 rows each).
struct K3Smem {
    __nv_bfloat16 p[2][2][64][72];    // 36.9 KB (2 heads)
    float m[2][64][68];               // 34.8 KB
    float st[2][2][64];               // x log2e
    float ld[2][2][64];               // -log2(denom)
    float ss[2][64];                  // x log2e
    unsigned long long dmb[2];
    unsigned long long cmb[2];
};
#define K3_TX_BYTES (64 * 256 + 2 * 9216 + 512 + 512)   // 35840

__device__ __forceinline__ void k3_issue(K3Smem* S, int ibase, int jt, int hg,
                                         int buf, uint32_t mb) {
    mbar_expect_tx(mb, K3_TX_BYTES);
    const int jbase = jt * 64;
#pragma unroll 4
    for (int r = 0; r < 64; r++)
        bulkcp(&S->m[buf][r][0], &g_mask[(size_t)(ibase + r) * NN + jbase], 256, mb);
#pragma unroll
    for (int h2 = 0; h2 < 2; h2++)
        bulkcp(&S->p[buf][h2][0][0], &g_projp[hg * 2 + h2][jt][0][0], 9216, mb);
    bulkcp(&S->st[buf][0][0], &g_stgt2[jt][hg * 2][0], 512, mb);
    bulkcp(&S->ld[buf][0][0], &g_nld2[jt][hg * 2][0], 512, mb);
}

__global__ void __launch_bounds__(256, 3) k3_mma(void) {
    extern __shared__ char smem_raw[];
    K3Smem* S = (K3Smem*)smem_raw;

    const int tid = threadIdx.x;
    const int ibase = blockIdx.x * 64;
    const int split = blockIdx.y;
    const int jt0 = split * 8;
    const int hg = blockIdx.z;
    const int wp = tid >> 5;
    const int lane = tid & 31;
    const int hl = wp >> 2;            // local head 0/1
    const int mq = (wp & 3) * 16;      // m-quarter: rows [mq, mq+16)
    const int g = lane >> 2;
    const int t = lane & 3;
    const int r0 = mq + g, r1 = r0 + 8;

    const uint32_t dmb0 = smem_u32(&S->dmb[0]);
    const uint32_t dmb1 = smem_u32(&S->dmb[1]);
    const uint32_t cmb0 = smem_u32(&S->cmb[0]);
    const uint32_t cmb1 = smem_u32(&S->cmb[1]);

    if (tid < 128) {   // stage ss (x log2e): 2 heads x 64 rows
        const int h2 = tid >> 6, ii = tid & 63;
        S->ss[h2][ii] = g_ssrc[(hg * 2 + h2) * NN + ibase + ii] * LOG2E;
    }
    if (tid == 0) {
        mbar_init(dmb0, 1);
        mbar_init(dmb1, 1);
        mbar_init(cmb0, 8);
        mbar_init(cmb1, 8);
        asm volatile("fence.proxy.async.shared::cta;" ::: "memory");
    }
    __syncthreads();
    if (tid == 0) {
        k3_issue(S, ibase, jt0 + 0, hg, 0, dmb0);
        k3_issue(S, ibase, jt0 + 1, hg, 1, dmb1);
    }

    const float ss0 = S->ss[hl][r0];
    const float ss1 = S->ss[hl][r1];

    float acc[8][4];
#pragma unroll
    for (int nt = 0; nt < 8; nt++)
#pragma unroll
        for (int q = 0; q < 4; q++) acc[nt][q] = 0.f;

    for (int jx = 0; jx < 8; jx++) {
        const int buf = jx & 1;
        mbar_wait(buf ? dmb1 : dmb0, (jx >> 1) & 1);

        const uint32_t p_base = smem_u32(&S->p[buf][hl][lane & 15][(lane >> 4) * 8]);

#pragma unroll
        for (int ks = 0; ks < 4; ks++) {
            // ---- produce this warp's A fragment in registers ----
            uint32_t a0, a1, a2, a3;
            {
                const int c = ks * 16 + 2 * t;
                float2 mm0 = *(const float2*)&S->m[buf][r0][c];
                float2 mm1 = *(const float2*)&S->m[buf][r1][c];
                float2 stv = *(const float2*)&S->st[buf][hl][c];
                float2 ldv = *(const float2*)&S->ld[buf][hl][c];
                float x00 = ss0 + stv.x; x00 = fmaxf(x00, 0.2f * x00);
                float x01 = ss0 + stv.y; x01 = fmaxf(x01, 0.2f * x01);
                float x10 = ss1 + stv.x; x10 = fmaxf(x10, 0.2f * x10);
                float x11 = ss1 + stv.y; x11 = fmaxf(x11, 0.2f * x11);
                a0 = packbf2(ex2f(fmaf(mm0.x, LOG2E, x00 + ldv.x)),
                             ex2f(fmaf(mm0.y, LOG2E, x01 + ldv.y)));
                a1 = packbf2(ex2f(fmaf(mm1.x, LOG2E, x10 + ldv.x)),
                             ex2f(fmaf(mm1.y, LOG2E, x11 + ldv.y)));
                mm0 = *(const float2*)&S->m[buf][r0][c + 8];
                mm1 = *(const float2*)&S->m[buf][r1][c + 8];
                stv = *(const float2*)&S->st[buf][hl][c + 8];
                ldv = *(const float2*)&S->ld[buf][hl][c + 8];
                x00 = ss0 + stv.x; x00 = fmaxf(x00, 0.2f * x00);
                x01 = ss0 + stv.y; x01 = fmaxf(x01, 0.2f * x01);
                x10 = ss1 + stv.x; x10 = fmaxf(x10, 0.2f * x10);
                x11 = ss1 + stv.y; x11 = fmaxf(x11, 0.2f * x11);
                a2 = packbf2(ex2f(fmaf(mm0.x, LOG2E, x00 + ldv.x)),
                             ex2f(fmaf(mm0.y, LOG2E, x01 + ldv.y)));
                a3 = packbf2(ex2f(fmaf(mm1.x, LOG2E, x10 + ldv.x)),
                             ex2f(fmaf(mm1.y, LOG2E, x11 + ldv.y)));
            }
            // ---- B frags + MMA ----
#pragma unroll
            for (int nb = 0; nb < 4; nb++) {
                uint32_t B0, B1, B2, B3;
                LDSM_X4T(B0, B1, B2, B3, p_base + ks * 16 * 144 + nb * 32);
                mma_bf16(acc[2 * nb], a0, a1, a2, a3, B0, B1);
                mma_bf16(acc[2 * nb + 1], a0, a1, a2, a3, B2, B3);
            }
        }

        if (lane == 0) mbar_arrive(buf ? cmb1 : cmb0);
        if (tid == 0 && jx + 2 < 8) {
            mbar_wait(buf ? cmb1 : cmb0, (jx >> 1) & 1);
            k3_issue(S, ibase, jt0 + jx + 2, hg, buf, buf ? dmb1 : dmb0);
        }
    }

    float* po = g_pout[split];
    const int h = hg * 2 + hl;
#pragma unroll
    for (int nt = 0; nt < 8; nt++) {
        const int f0 = nt * 8 + t * 2;
        const int n0 = ibase + r0;
        const int n1 = ibase + r1;
#pragma unroll
        for (int q = 0; q < 4; q++) {
            const int n = (q >= 2) ? n1 : n0;
            const int f = f0 + (q & 1);
            po[n * (HH * F_OUT) + h * F_OUT + f] = acc[nt][q];
        }
    }
}

// ---------------- k4: combine 8 splits + skip + ELU ------------------------
__global__ void k4_combine(float* __restrict__ out) {
    const int i4 = (blockIdx.x * 256 + threadIdx.x) * 4;
    float4 a = *(const float4*)&g_skip[i4];
#pragma unroll
    for (int s = 0; s < 8; s++) {
        const float4 p = *(const float4*)&g_pout[s][i4];
        a.x += p.x; a.y += p.y; a.z += p.z; a.w += p.w;
    }
    float4 o;
    o.x = (a.x > 0.f) ? a.x : (__expf(a.x) - 1.f);
    o.y = (a.y > 0.f) ? a.y : (__expf(a.y) - 1.f);
    o.z = (a.z > 0.f) ? a.z : (__expf(a.z) - 1.f);
    o.w = (a.w > 0.f) ? a.w : (__expf(a.w) - 1.f);
    *(float4*)&out[i4] = o;
}

// ---------------- launch ---------------------------------------------------
extern "C" void kernel_launch(void* const* d_in, const int* in_sizes, int n_in,
                              void* d_out, int out_size) {
    const float* nodes = (const float*)d_in[0];
    const float* deg   = (const float*)d_in[1];
    const float* bond  = (const float*)d_in[3];
    const float* pp    = (const float*)d_in[4];
    const float* wsrc  = (const float*)d_in[5];
    const float* wtgt  = (const float*)d_in[6];
    const float* skw   = (const float*)d_in[7];
    const int*   cut   = (const int*)d_in[8];

    float* out    = (float*)d_out;
    float* ln_out = (float*)d_out + (size_t)NN * HH * F_OUT;

    const int k3_smem = (int)sizeof(K3Smem);
    cudaFuncSetAttribute(k3_mma, cudaFuncAttributeMaxDynamicSharedMemorySize, k3_smem);

    k0_fused<<<256, 256>>>(nodes, pp, skw, wsrc, wtgt);
    k1_mask_ln<<<NN, 512>>>(deg, bond, cut, ln_out);
    k2_colsum<<<dim3(16, 32), 256>>>();
    k2b_reduce<<<64, 256>>>();
    k3_mma<<<dim3(64, 8, 2), 256, k3_smem>>>();
    k4_combine<<<1024, 256>>>(out);
}

// round 12
// speedup vs baseline: 1.1475x; 1.1475x over previous
#include <cuda_runtime.h>
#include <cuda_bf16.h>
#include <math.h>
#include <stdint.h>

#define NN 4096
#define F_IN 128
#define F_OUT 64
#define HH 4
#define NEG_INF -1e9f
#define LN_EPS 1e-5f
#define NTILE 64
#define LOG2E 1.4426950408889634f

// ---------------- scratch (device globals: allocation-free) ----------------
__device__ float g_mask[(size_t)NN * NN];                      // 64 MB
__device__ __align__(16) __nv_bfloat16 g_projp[HH][NTILE][64][72];
__device__ float g_skip[NN * HH * F_OUT];
__device__ float g_ssrc[HH * NN];                              // raw
__device__ __align__(16) float g_stgt2[NTILE][HH][64];         // x log2e
__device__ __align__(16) float g_part[128 * HH * NN];          // 32MB partials
__device__ __align__(16) float g_nld2[NTILE][HH][64];          // -log2(denom)
__device__ float g_pout[4][NN * HH * F_OUT];                   // j-split partials

// ---------------- asm helpers ----------------------------------------------
__device__ __forceinline__ uint32_t smem_u32(const void* p) {
    return (uint32_t)__cvta_generic_to_shared(p);
}
__device__ __forceinline__ void bulkcp(void* s, const void* g, int bytes,
                                       uint32_t mbar) {
    asm volatile(
        "cp.async.bulk.shared::cta.global.mbarrier::complete_tx::bytes "
        "[%0], [%1], %2, [%3];"
        :: "r"(smem_u32(s)), "l"(g), "r"(bytes), "r"(mbar) : "memory");
}
__device__ __forceinline__ void mbar_init(uint32_t mbar, uint32_t cnt) {
    asm volatile("mbarrier.init.shared.b64 [%0], %1;" :: "r"(mbar), "r"(cnt) : "memory");
}
__device__ __forceinline__ void mbar_expect_tx(uint32_t mbar, uint32_t bytes) {
    asm volatile("mbarrier.arrive.expect_tx.shared.b64 _, [%0], %1;"
                 :: "r"(mbar), "r"(bytes) : "memory");
}
__device__ __forceinline__ void mbar_arrive(uint32_t mbar) {
    asm volatile("mbarrier.arrive.release.cta.shared::cta.b64 _, [%0];"
                 :: "r"(mbar) : "memory");
}
__device__ __forceinline__ void mbar_wait(uint32_t mbar, uint32_t parity) {
    asm volatile(
        "{\n\t.reg .pred P1;\n\t"
        "WAIT_LOOP_%=:\n\t"
        "mbarrier.try_wait.parity.acquire.cta.shared::cta.b64 P1, [%0], %1, 0x989680;\n\t"
        "@P1 bra.uni WAIT_DONE_%=;\n\t"
        "bra.uni WAIT_LOOP_%=;\n\t"
        "WAIT_DONE_%=:\n\t}"
        :: "r"(mbar), "r"(parity) : "memory");
}
__device__ __forceinline__ float ex2f(float x) {
    float r;
    asm("ex2.approx.ftz.f32 %0, %1;" : "=f"(r) : "f"(x));
    return r;
}
__device__ __forceinline__ uint32_t packbf2(float lo, float hi) {
    __nv_bfloat162 v = __floats2bfloat162_rn(lo, hi);
    return *(uint32_t*)&v;
}

#define LDSM_X4T(r0, r1, r2, r3, a) \
    asm volatile("ldmatrix.sync.aligned.m8n8.x4.trans.shared.b16 {%0,%1,%2,%3}, [%4];" \
                 : "=r"(r0), "=r"(r1), "=r"(r2), "=r"(r3) : "r"(a))

__device__ __forceinline__ void mma_bf16(float* c, uint32_t a0, uint32_t a1,
                                         uint32_t a2, uint32_t a3,
                                         uint32_t b0, uint32_t b1) {
    asm volatile(
        "mma.sync.aligned.m16n8k16.row.col.f32.bf16.bf16.f32 "
        "{%0,%1,%2,%3}, {%4,%5,%6,%7}, {%8,%9}, {%0,%1,%2,%3};"
        : "+f"(c[0]), "+f"(c[1]), "+f"(c[2]), "+f"(c[3])
        : "r"(a0), "r"(a1), "r"(a2), "r"(a3), "r"(b0), "r"(b1));
}

// ---------------- k0: fused proj(bf16) + scores + skip ---------------------
__global__ void k0_fused(const float* __restrict__ nodes,
                         const float* __restrict__ pp,
                         const float* __restrict__ skw,
                         const float* __restrict__ wsrc,
                         const float* __restrict__ wtgt) {
    __shared__ float xs[16][F_IN];
    __shared__ float red[2][2][HH][16];
    const int nbase = blockIdx.x * 16;
    const int tid = threadIdx.x;
    for (int q = tid; q < 16 * F_IN; q += 256)
        xs[q >> 7][q & 127] = nodes[nbase * F_IN + q];
    __syncthreads();

    const int h = tid >> 6, o = tid & 63;
    const int lane = tid & 31, half = (tid >> 5) & 1;
    const int jt = nbase >> 6, rbase = nbase & 63;

    float acc[16];
#pragma unroll
    for (int k = 0; k < 16; k++) acc[k] = 0.f;
    for (int f = 0; f < F_IN; f++) {
        float w = pp[h * F_IN * F_OUT + f * F_OUT + o];
#pragma unroll
        for (int k = 0; k < 16; k++) acc[k] += xs[k][f] * w;
    }
#pragma unroll
    for (int k = 0; k < 16; k++)
        g_projp[h][jt][rbase + k][o] = __float2bfloat16_rn(acc[k]);

    {
        const float ws = wsrc[h * F_OUT + o];
        const float wt = wtgt[h * F_OUT + o];
#pragma unroll
        for (int k = 0; k < 16; k++) {
            float s = acc[k] * ws, t = acc[k] * wt;
#pragma unroll
            for (int off = 16; off; off >>= 1) {
                s += __shfl_down_sync(0xffffffffu, s, off);
                t += __shfl_down_sync(0xffffffffu, t, off);
            }
            if (lane == 0) { red[0][half][h][k] = s; red[1][half][h][k] = t; }
        }
    }
    __syncthreads();
    if (tid < 128) {
        const int h2 = tid >> 5, k = (tid >> 1) & 15, sel = tid & 1;
        const float v = red[sel][0][h2][k] + red[sel][1][h2][k];
        const int n = nbase + k;
        if (sel == 0) g_ssrc[h2 * NN + n] = v;
        else          g_stgt2[n >> 6][h2][n & 63] = v * LOG2E;
    }

#pragma unroll
    for (int k = 0; k < 16; k++) acc[k] = 0.f;
    for (int f = 0; f < F_IN; f++) {
        float w = skw[tid * F_IN + f];
#pragma unroll
        for (int k = 0; k < 16; k++) acc[k] += xs[k][f] * w;
    }
#pragma unroll
    for (int k = 0; k < 16; k++)
        g_skip[(nbase + k) * (HH * F_OUT) + tid] = acc[k];
}

// ---------------- kA: mask compute + column exp partial sums (fused) -------
// grid 128 (i-chunks of 32 rows), block 512. Thread owns 8 j-cols x 4 heads
// in REGISTERS; reads deg/bond coalesced, writes mask once.
__global__ void __launch_bounds__(512) kA_mask_colsum(
        const float* __restrict__ deg,
        const float* __restrict__ bond,
        const int* __restrict__ cutoff_p) {
    const int tid = threadIdx.x;
    const int ibase = blockIdx.x * 32;
    const int j0 = tid * 8;
    const int jt = j0 >> 6, jw = j0 & 63;
    const float cut = (float)(*cutoff_p);

    __shared__ float ss[HH][32];
    if (tid < HH * 32)
        ss[tid >> 5][tid & 31] =
            g_ssrc[(tid >> 5) * NN + ibase + (tid & 31)] * LOG2E;

    float st[HH][8];
#pragma unroll
    for (int h = 0; h < HH; h++) {
        const float4 s0 = *(const float4*)&g_stgt2[jt][h][jw];
        const float4 s1 = *(const float4*)&g_stgt2[jt][h][jw + 4];
        st[h][0] = s0.x; st[h][1] = s0.y; st[h][2] = s0.z; st[h][3] = s0.w;
        st[h][4] = s1.x; st[h][5] = s1.y; st[h][6] = s1.z; st[h][7] = s1.w;
    }
    float acc[HH][8];
#pragma unroll
    for (int h = 0; h < HH; h++)
#pragma unroll
        for (int q = 0; q < 8; q++) acc[h][q] = 0.f;
    __syncthreads();

    for (int r = 0; r < 32; r++) {
        const size_t base = (size_t)(ibase + r) * NN + j0;
        const float4 d0 = __ldcs((const float4*)&deg[base]);
        const float4 d1 = __ldcs((const float4*)&deg[base + 4]);
        const float4 b0 = __ldcs((const float4*)&bond[base]);
        const float4 b1 = __ldcs((const float4*)&bond[base + 4]);
        float m[8];
        {
            float w;
            w = d0.x + b0.x; m[0] = (w > 0.f) ? w : ((b0.x > cut) ? (b0.x + w) : NEG_INF);
            w = d0.y + b0.y; m[1] = (w > 0.f) ? w : ((b0.y > cut) ? (b0.y + w) : NEG_INF);
            w = d0.z + b0.z; m[2] = (w > 0.f) ? w : ((b0.z > cut) ? (b0.z + w) : NEG_INF);
            w = d0.w + b0.w; m[3] = (w > 0.f) ? w : ((b0.w > cut) ? (b0.w + w) : NEG_INF);
            w = d1.x + b1.x; m[4] = (w > 0.f) ? w : ((b1.x > cut) ? (b1.x + w) : NEG_INF);
            w = d1.y + b1.y; m[5] = (w > 0.f) ? w : ((b1.y > cut) ? (b1.y + w) : NEG_INF);
            w = d1.z + b1.z; m[6] = (w > 0.f) ? w : ((b1.z > cut) ? (b1.z + w) : NEG_INF);
            w = d1.w + b1.w; m[7] = (w > 0.f) ? w : ((b1.w > cut) ? (b1.w + w) : NEG_INF);
        }
        *(float4*)&g_mask[base]     = make_float4(m[0], m[1], m[2], m[3]);
        *(float4*)&g_mask[base + 4] = make_float4(m[4], m[5], m[6], m[7]);
#pragma unroll
        for (int h = 0; h < HH; h++) {
            const float ssv = ss[h][r];
#pragma unroll
            for (int q = 0; q < 8; q++) {
                float x = ssv + st[h][q];
                x = fmaxf(x, 0.2f * x);
                acc[h][q] += ex2f(fmaf(m[q], LOG2E, x));
            }
        }
    }
#pragma unroll
    for (int h = 0; h < HH; h++) {
        float* p = &g_part[((size_t)blockIdx.x * HH + h) * NN + j0];
        *(float4*)&p[0] = make_float4(acc[h][0], acc[h][1], acc[h][2], acc[h][3]);
        *(float4*)&p[4] = make_float4(acc[h][4], acc[h][5], acc[h][6], acc[h][7]);
    }
}

// ---------------- k2b: reduce 128 chunks -> -log2(denom) -------------------
__global__ void k2b_reduce() {
    const int id = blockIdx.x * 256 + threadIdx.x;   // h*NN + j
    float s0 = 0.f, s1 = 0.f, s2 = 0.f, s3 = 0.f;
#pragma unroll
    for (int c = 0; c < 128; c += 4) {
        s0 += g_part[(size_t)(c + 0) * HH * NN + id];
        s1 += g_part[(size_t)(c + 1) * HH * NN + id];
        s2 += g_part[(size_t)(c + 2) * HH * NN + id];
        s3 += g_part[(size_t)(c + 3) * HH * NN + id];
    }
    const float s = (s0 + s1) + (s2 + s3);
    const int h = id >> 12, j = id & (NN - 1);
    g_nld2[j >> 6][h][j & 63] = -__log2f(s);
}

// ---------------- k3: M=64 bf16 mma, register A-frags, mbar pipeline -------
// (R10 best config, unchanged) grid (64, 4), block 256 = 8 warps.
struct K3Smem {
    __nv_bfloat16 p[2][HH][64][72];   // 73.7 KB
    float m[2][64][68];               // 34.8 KB
    float st[2][HH][64];              // x log2e
    float ld[2][HH][64];              // -log2(denom)
    float ss[HH][64];                 // x log2e
    unsigned long long dmb[2];
    unsigned long long cmb[2];
};
#define K3_TX_BYTES (64 * 256 + HH * 9216 + 1024 + 1024)   // 55296

__device__ __forceinline__ void k3_issue(K3Smem* S, int ibase, int jt, int buf,
                                         uint32_t mb) {
    mbar_expect_tx(mb, K3_TX_BYTES);
    const int jbase = jt * 64;
#pragma unroll 4
    for (int r = 0; r < 64; r++)
        bulkcp(&S->m[buf][r][0], &g_mask[(size_t)(ibase + r) * NN + jbase], 256, mb);
#pragma unroll
    for (int h2 = 0; h2 < HH; h2++)
        bulkcp(&S->p[buf][h2][0][0], &g_projp[h2][jt][0][0], 9216, mb);
    bulkcp(&S->st[buf][0][0], &g_stgt2[jt][0][0], 1024, mb);
    bulkcp(&S->ld[buf][0][0], &g_nld2[jt][0][0], 1024, mb);
}

__global__ void __launch_bounds__(256, 2) k3_mma(void) {
    extern __shared__ char smem_raw[];
    K3Smem* S = (K3Smem*)smem_raw;

    const int tid = threadIdx.x;
    const int ibase = blockIdx.x * 64;
    const int split = blockIdx.y;
    const int jt0 = split * 16;
    const int wp = tid >> 5;
    const int lane = tid & 31;
    const int h = wp >> 1;
    const int mh = (wp & 1) * 32;
    const int g = lane >> 2;
    const int t = lane & 3;
    const int rA0 = mh + g,      rA1 = rA0 + 8;
    const int rB0 = mh + 16 + g, rB1 = rB0 + 8;

    const uint32_t dmb0 = smem_u32(&S->dmb[0]);
    const uint32_t dmb1 = smem_u32(&S->dmb[1]);
    const uint32_t cmb0 = smem_u32(&S->cmb[0]);
    const uint32_t cmb1 = smem_u32(&S->cmb[1]);

    {
        const int h2 = tid >> 6, ii = tid & 63;
        S->ss[h2][ii] = g_ssrc[h2 * NN + ibase + ii] * LOG2E;
    }
    if (tid == 0) {
        mbar_init(dmb0, 1);
        mbar_init(dmb1, 1);
        mbar_init(cmb0, 8);
        mbar_init(cmb1, 8);
        asm volatile("fence.proxy.async.shared::cta;" ::: "memory");
    }
    __syncthreads();
    if (tid == 0) {
        k3_issue(S, ibase, jt0 + 0, 0, dmb0);
        k3_issue(S, ibase, jt0 + 1, 1, dmb1);
    }

    const float ssA0 = S->ss[h][rA0], ssA1 = S->ss[h][rA1];
    const float ssB0 = S->ss[h][rB0], ssB1 = S->ss[h][rB1];

    float acc0[8][4], acc1[8][4];
#pragma unroll
    for (int nt = 0; nt < 8; nt++)
#pragma unroll
        for (int q = 0; q < 4; q++) { acc0[nt][q] = 0.f; acc1[nt][q] = 0.f; }

    for (int jx = 0; jx < 16; jx++) {
        const int buf = jx & 1;
        mbar_wait(buf ? dmb1 : dmb0, (jx >> 1) & 1);

        const uint32_t p_base = smem_u32(&S->p[buf][h][lane & 15][(lane >> 4) * 8]);

#pragma unroll
        for (int ks = 0; ks < 4; ks++) {
            const int c = ks * 16 + 2 * t;
            const float2 stv  = *(const float2*)&S->st[buf][h][c];
            const float2 ldv  = *(const float2*)&S->ld[buf][h][c];
            const float2 stv2 = *(const float2*)&S->st[buf][h][c + 8];
            const float2 ldv2 = *(const float2*)&S->ld[buf][h][c + 8];

            uint32_t a0, a1, a2, a3, b0, b1, b2, b3;
            {
                float2 mm0 = *(const float2*)&S->m[buf][rA0][c];
                float2 mm1 = *(const float2*)&S->m[buf][rA1][c];
                float x00 = ssA0 + stv.x; x00 = fmaxf(x00, 0.2f * x00);
                float x01 = ssA0 + stv.y; x01 = fmaxf(x01, 0.2f * x01);
                float x10 = ssA1 + stv.x; x10 = fmaxf(x10, 0.2f * x10);
                float x11 = ssA1 + stv.y; x11 = fmaxf(x11, 0.2f * x11);
                a0 = packbf2(ex2f(fmaf(mm0.x, LOG2E, x00 + ldv.x)),
                             ex2f(fmaf(mm0.y, LOG2E, x01 + ldv.y)));
                a1 = packbf2(ex2f(fmaf(mm1.x, LOG2E, x10 + ldv.x)),
                             ex2f(fmaf(mm1.y, LOG2E, x11 + ldv.y)));
                mm0 = *(const float2*)&S->m[buf][rA0][c + 8];
                mm1 = *(const float2*)&S->m[buf][rA1][c + 8];
                x00 = ssA0 + stv2.x; x00 = fmaxf(x00, 0.2f * x00);
                x01 = ssA0 + stv2.y; x01 = fmaxf(x01, 0.2f * x01);
                x10 = ssA1 + stv2.x; x10 = fmaxf(x10, 0.2f * x10);
                x11 = ssA1 + stv2.y; x11 = fmaxf(x11, 0.2f * x11);
                a2 = packbf2(ex2f(fmaf(mm0.x, LOG2E, x00 + ldv2.x)),
                             ex2f(fmaf(mm0.y, LOG2E, x01 + ldv2.y)));
                a3 = packbf2(ex2f(fmaf(mm1.x, LOG2E, x10 + ldv2.x)),
                             ex2f(fmaf(mm1.y, LOG2E, x11 + ldv2.y)));
            }
            {
                float2 mm0 = *(const float2*)&S->m[buf][rB0][c];
                float2 mm1 = *(const float2*)&S->m[buf][rB1][c];
                float x00 = ssB0 + stv.x; x00 = fmaxf(x00, 0.2f * x00);
                float x01 = ssB0 + stv.y; x01 = fmaxf(x01, 0.2f * x01);
                float x10 = ssB1 + stv.x; x10 = fmaxf(x10, 0.2f * x10);
                float x11 = ssB1 + stv.y; x11 = fmaxf(x11, 0.2f * x11);
                b0 = packbf2(ex2f(fmaf(mm0.x, LOG2E, x00 + ldv.x)),
                             ex2f(fmaf(mm0.y, LOG2E, x01 + ldv.y)));
                b1 = packbf2(ex2f(fmaf(mm1.x, LOG2E, x10 + ldv.x)),
                             ex2f(fmaf(mm1.y, LOG2E, x11 + ldv.y)));
                mm0 = *(const float2*)&S->m[buf][rB0][c + 8];
                mm1 = *(const float2*)&S->m[buf][rB1][c + 8];
                x00 = ssB0 + stv2.x; x00 = fmaxf(x00, 0.2f * x00);
                x01 = ssB0 + stv2.y; x01 = fmaxf(x01, 0.2f * x01);
                x10 = ssB1 + stv2.x; x10 = fmaxf(x10, 0.2f * x10);
                x11 = ssB1 + stv2.y; x11 = fmaxf(x11, 0.2f * x11);
                b2 = packbf2(ex2f(fmaf(mm0.x, LOG2E, x00 + ldv2.x)),
                             ex2f(fmaf(mm0.y, LOG2E, x01 + ldv2.y)));
                b3 = packbf2(ex2f(fmaf(mm1.x, LOG2E, x10 + ldv2.x)),
                             ex2f(fmaf(mm1.y, LOG2E, x11 + ldv2.y)));
            }
#pragma unroll
            for (int nb = 0; nb < 4; nb++) {
                uint32_t B0, B1, B2, B3;
                LDSM_X4T(B0, B1, B2, B3, p_base + ks * 16 * 144 + nb * 32);
                mma_bf16(acc0[2 * nb],     a0, a1, a2, a3, B0, B1);
                mma_bf16(acc0[2 * nb + 1], a0, a1, a2, a3, B2, B3);
                mma_bf16(acc1[2 * nb],     b0, b1, b2, b3, B0, B1);
                mma_bf16(acc1[2 * nb + 1], b0, b1, b2, b3, B2, B3);
            }
        }

        if (lane == 0) mbar_arrive(buf ? cmb1 : cmb0);
        if (tid == 0 && jx + 2 < 16) {
            mbar_wait(buf ? cmb1 : cmb0, (jx >> 1) & 1);
            k3_issue(S, ibase, jt0 + jx + 2, buf, buf ? dmb1 : dmb0);
        }
    }

    float* po = g_pout[split];
#pragma unroll
    for (int nt = 0; nt < 8; nt++) {
        const int f0 = nt * 8 + t * 2;
#pragma unroll
        for (int q = 0; q < 4; q++) {
            const int f = f0 + (q & 1);
            const int nA = ibase + ((q >= 2) ? rA1 : rA0);
            const int nB = ibase + ((q >= 2) ? rB1 : rB0);
            po[nA * (HH * F_OUT) + h * F_OUT + f] = acc0[nt][q];
            po[nB * (HH * F_OUT) + h * F_OUT + f] = acc1[nt][q];
        }
    }
}

// ---------------- k1b: row LayerNorm from mask -----------------------------
__global__ void k1b_ln(float* __restrict__ ln_out) {
    const int i = blockIdx.x;
    const int tid = threadIdx.x;
    const size_t row = (size_t)i * NN;

    float4 m4[2];
    float s = 0.f, s2 = 0.f;
#pragma unroll
    for (int k = 0; k < 2; k++) {
        const int j4 = (k * 512 + tid) * 4;
        const float4 m = __ldcs((const float4*)&g_mask[row + j4]);
        m4[k] = m;
        s  += (m.x + m.y) + (m.z + m.w);
        s2 += (m.x * m.x + m.y * m.y) + (m.z * m.z + m.w * m.w);
    }
    __shared__ float rs[16], rs2[16];
    const int lane = tid & 31, wp = tid >> 5;
#pragma unroll
    for (int off = 16; off; off >>= 1) {
        s  += __shfl_down_sync(0xffffffffu, s, off);
        s2 += __shfl_down_sync(0xffffffffu, s2, off);
    }
    if (lane == 0) { rs[wp] = s; rs2[wp] = s2; }
    __syncthreads();
    if (wp == 0) {
        float a  = (lane < 16) ? rs[lane] : 0.f;
        float a2 = (lane < 16) ? rs2[lane] : 0.f;
#pragma unroll
        for (int off = 8; off; off >>= 1) {
            a  += __shfl_down_sync(0xffffffffu, a, off);
            a2 += __shfl_down_sync(0xffffffffu, a2, off);
        }
        if (lane == 0) { rs[0] = a; rs2[0] = a2; }
    }
    __syncthreads();
    const float mu  = rs[0] * (1.0f / NN);
    const float var = fmaxf(rs2[0] * (1.0f / NN) - mu * mu, 0.f);
    const float rstd = 1.0f / sqrtf(var + LN_EPS);
#pragma unroll
    for (int k = 0; k < 2; k++) {
        const int j4 = (k * 512 + tid) * 4;
        float4 o4;
        o4.x = (m4[k].x - mu) * rstd;
        o4.y = (m4[k].y - mu) * rstd;
        o4.z = (m4[k].z - mu) * rstd;
        o4.w = (m4[k].w - mu) * rstd;
        __stcs((float4*)&ln_out[row + j4], o4);
    }
}

// ---------------- k4: combine 4 splits + skip + ELU ------------------------
__global__ void k4_combine(float* __restrict__ out) {
    const int i4 = (blockIdx.x * 256 + threadIdx.x) * 4;
    const float4 p0 = *(const float4*)&g_pout[0][i4];
    const float4 p1 = *(const float4*)&g_pout[1][i4];
    const float4 p2 = *(const float4*)&g_pout[2][i4];
    const float4 p3 = *(const float4*)&g_pout[3][i4];
    const float4 sk = *(const float4*)&g_skip[i4];
    float4 o;
    float v;
    v = (p0.x + p1.x) + (p2.x + p3.x) + sk.x; o.x = (v > 0.f) ? v : (__expf(v) - 1.f);
    v = (p0.y + p1.y) + (p2.y + p3.y) + sk.y; o.y = (v > 0.f) ? v : (__expf(v) - 1.f);
    v = (p0.z + p1.z) + (p2.z + p3.z) + sk.z; o.z = (v > 0.f) ? v : (__expf(v) - 1.f);
    v = (p0.w + p1.w) + (p2.w + p3.w) + sk.w; o.w = (v > 0.f) ? v : (__expf(v) - 1.f);
    *(float4*)&out[i4] = o;
}

// ---------------- launch ---------------------------------------------------
extern "C" void kernel_launch(void* const* d_in, const int* in_sizes, int n_in,
                              void* d_out, int out_size) {
    const float* nodes = (const float*)d_in[0];
    const float* deg   = (const float*)d_in[1];
    const float* bond  = (const float*)d_in[3];
    const float* pp    = (const float*)d_in[4];
    const float* wsrc  = (const float*)d_in[5];
    const float* wtgt  = (const float*)d_in[6];
    const float* skw   = (const float*)d_in[7];
    const int*   cut   = (const int*)d_in[8];

    float* out    = (float*)d_out;
    float* ln_out = (float*)d_out + (size_t)NN * HH * F_OUT;

    const int k3_smem = (int)sizeof(K3Smem);
    cudaFuncSetAttribute(k3_mma, cudaFuncAttributeMaxDynamicSharedMemorySize, k3_smem);

    k0_fused<<<256, 256>>>(nodes, pp, skw, wsrc, wtgt);
    kA_mask_colsum<<<128, 512>>>(deg, bond, cut);
    k2b_reduce<<<64, 256>>>();
    k3_mma<<<dim3(64, 4), 256, k3_smem>>>();      // 4th launch -> profiled
    k1b_ln<<<NN, 512>>>(ln_out);
    k4_combine<<<1024, 256>>>(out);
}

// round 13
// speedup vs baseline: 1.1617x; 1.0123x over previous
#include <cuda_runtime.h>
#include <cuda_bf16.h>
#include <math.h>
#include <stdint.h>

#define NN 4096
#define F_IN 128
#define F_OUT 64
#define HH 4
#define NEG_INF -1e9f
#define LN_EPS 1e-5f
#define NTILE 64
#define LOG2E 1.4426950408889634f

// ---------------- scratch (device globals: allocation-free) ----------------
__device__ float g_mask[(size_t)NN * NN];                      // 64 MB
__device__ __align__(16) __nv_bfloat16 g_projp[HH][NTILE][64][72];
__device__ float g_skip[NN * HH * F_OUT];
__device__ float g_ssrc[HH * NN];                              // raw
__device__ __align__(16) float g_stgt2[NTILE][HH][64];         // x log2e
__device__ __align__(16) float g_part[128 * HH * NN];          // 32MB partials
__device__ __align__(16) float g_nld2[NTILE][HH][64];          // -log2(denom)
__device__ float g_pout[4][NN * HH * F_OUT];                   // j-split partials

// ---------------- asm helpers ----------------------------------------------
__device__ __forceinline__ uint32_t smem_u32(const void* p) {
    return (uint32_t)__cvta_generic_to_shared(p);
}
__device__ __forceinline__ void bulkcp(void* s, const void* g, int bytes,
                                       uint32_t mbar) {
    asm volatile(
        "cp.async.bulk.shared::cta.global.mbarrier::complete_tx::bytes "
        "[%0], [%1], %2, [%3];"
        :: "r"(smem_u32(s)), "l"(g), "r"(bytes), "r"(mbar) : "memory");
}
__device__ __forceinline__ void mbar_init(uint32_t mbar, uint32_t cnt) {
    asm volatile("mbarrier.init.shared.b64 [%0], %1;" :: "r"(mbar), "r"(cnt) : "memory");
}
__device__ __forceinline__ void mbar_expect_tx(uint32_t mbar, uint32_t bytes) {
    asm volatile("mbarrier.arrive.expect_tx.shared.b64 _, [%0], %1;"
                 :: "r"(mbar), "r"(bytes) : "memory");
}
__device__ __forceinline__ void mbar_arrive(uint32_t mbar) {
    asm volatile("mbarrier.arrive.release.cta.shared::cta.b64 _, [%0];"
                 :: "r"(mbar) : "memory");
}
__device__ __forceinline__ void mbar_wait(uint32_t mbar, uint32_t parity) {
    asm volatile(
        "{\n\t.reg .pred P1;\n\t"
        "WAIT_LOOP_%=:\n\t"
        "mbarrier.try_wait.parity.acquire.cta.shared::cta.b64 P1, [%0], %1, 0x989680;\n\t"
        "@P1 bra.uni WAIT_DONE_%=;\n\t"
        "bra.uni WAIT_LOOP_%=;\n\t"
        "WAIT_DONE_%=:\n\t}"
        :: "r"(mbar), "r"(parity) : "memory");
}
__device__ __forceinline__ float ex2f(float x) {
    float r;
    asm("ex2.approx.ftz.f32 %0, %1;" : "=f"(r) : "f"(x));
    return r;
}
__device__ __forceinline__ uint32_t packbf2(float lo, float hi) {
    __nv_bfloat162 v = __floats2bfloat162_rn(lo, hi);
    return *(uint32_t*)&v;
}

#define LDSM_X4T(r0, r1, r2, r3, a) \
    asm volatile("ldmatrix.sync.aligned.m8n8.x4.trans.shared.b16 {%0,%1,%2,%3}, [%4];" \
                 : "=r"(r0), "=r"(r1), "=r"(r2), "=r"(r3) : "r"(a))

__device__ __forceinline__ void mma_bf16(float* c, uint32_t a0, uint32_t a1,
                                         uint32_t a2, uint32_t a3,
                                         uint32_t b0, uint32_t b1) {
    asm volatile(
        "mma.sync.aligned.m16n8k16.row.col.f32.bf16.bf16.f32 "
        "{%0,%1,%2,%3}, {%4,%5,%6,%7}, {%8,%9}, {%0,%1,%2,%3};"
        : "+f"(c[0]), "+f"(c[1]), "+f"(c[2]), "+f"(c[3])
        : "r"(a0), "r"(a1), "r"(a2), "r"(a3), "r"(b0), "r"(b1));
}

// ---------------- k0: fused proj(bf16) + scores + skip ---------------------
__global__ void k0_fused(const float* __restrict__ nodes,
                         const float* __restrict__ pp,
                         const float* __restrict__ skw,
                         const float* __restrict__ wsrc,
                         const float* __restrict__ wtgt) {
    __shared__ float xs[16][F_IN];
    __shared__ float red[2][2][HH][16];
    const int nbase = blockIdx.x * 16;
    const int tid = threadIdx.x;
    for (int q = tid; q < 16 * F_IN; q += 256)
        xs[q >> 7][q & 127] = nodes[nbase * F_IN + q];
    __syncthreads();

    const int h = tid >> 6, o = tid & 63;
    const int lane = tid & 31, half = (tid >> 5) & 1;
    const int jt = nbase >> 6, rbase = nbase & 63;

    float acc[16];
#pragma unroll
    for (int k = 0; k < 16; k++) acc[k] = 0.f;
    for (int f = 0; f < F_IN; f++) {
        float w = pp[h * F_IN * F_OUT + f * F_OUT + o];
#pragma unroll
        for (int k = 0; k < 16; k++) acc[k] += xs[k][f] * w;
    }
#pragma unroll
    for (int k = 0; k < 16; k++)
        g_projp[h][jt][rbase + k][o] = __float2bfloat16_rn(acc[k]);

    {
        const float ws = wsrc[h * F_OUT + o];
        const float wt = wtgt[h * F_OUT + o];
#pragma unroll
        for (int k = 0; k < 16; k++) {
            float s = acc[k] * ws, t = acc[k] * wt;
#pragma unroll
            for (int off = 16; off; off >>= 1) {
                s += __shfl_down_sync(0xffffffffu, s, off);
                t += __shfl_down_sync(0xffffffffu, t, off);
            }
            if (lane == 0) { red[0][half][h][k] = s; red[1][half][h][k] = t; }
        }
    }
    __syncthreads();
    if (tid < 128) {
        const int h2 = tid >> 5, k = (tid >> 1) & 15, sel = tid & 1;
        const float v = red[sel][0][h2][k] + red[sel][1][h2][k];
        const int n = nbase + k;
        if (sel == 0) g_ssrc[h2 * NN + n] = v;
        else          g_stgt2[n >> 6][h2][n & 63] = v * LOG2E;
    }

#pragma unroll
    for (int k = 0; k < 16; k++) acc[k] = 0.f;
    for (int f = 0; f < F_IN; f++) {
        float w = skw[tid * F_IN + f];
#pragma unroll
        for (int k = 0; k < 16; k++) acc[k] += xs[k][f] * w;
    }
#pragma unroll
    for (int k = 0; k < 16; k++)
        g_skip[(nbase + k) * (HH * F_OUT) + tid] = acc[k];
}

// ---------------- kA: mask compute + column exp partial sums (fused) -------
// grid (128 i-chunks, 2 j-halves), block 512. Thread owns 4 j-cols x 4 heads
// in registers; next-row prefetch keeps loads off the exp critical path.
__global__ void __launch_bounds__(512, 2) kA_mask_colsum(
        const float* __restrict__ deg,
        const float* __restrict__ bond,
        const int* __restrict__ cutoff_p) {
    const int tid = threadIdx.x;
    const int ibase = blockIdx.x * 32;
    const int j0 = blockIdx.y * 2048 + tid * 4;
    const int jt = j0 >> 6, jw = j0 & 63;
    const float cut = (float)(*cutoff_p);

    __shared__ float ss[HH][32];
    if (tid < HH * 32)
        ss[tid >> 5][tid & 31] =
            g_ssrc[(tid >> 5) * NN + ibase + (tid & 31)] * LOG2E;

    float st[HH][4];
#pragma unroll
    for (int h = 0; h < HH; h++) {
        const float4 s0 = *(const float4*)&g_stgt2[jt][h][jw];
        st[h][0] = s0.x; st[h][1] = s0.y; st[h][2] = s0.z; st[h][3] = s0.w;
    }
    float acc[HH][4];
#pragma unroll
    for (int h = 0; h < HH; h++)
#pragma unroll
        for (int q = 0; q < 4; q++) acc[h][q] = 0.f;
    __syncthreads();

    float4 d = __ldcs((const float4*)&deg[(size_t)ibase * NN + j0]);
    float4 b = __ldcs((const float4*)&bond[(size_t)ibase * NN + j0]);

    for (int r = 0; r < 32; r++) {
        float4 nd, nb;
        if (r + 1 < 32) {
            const size_t nbase_ = (size_t)(ibase + r + 1) * NN + j0;
            nd = __ldcs((const float4*)&deg[nbase_]);
            nb = __ldcs((const float4*)&bond[nbase_]);
        }
        float m[4];
        {
            float w;
            w = d.x + b.x; m[0] = (w > 0.f) ? w : ((b.x > cut) ? (b.x + w) : NEG_INF);
            w = d.y + b.y; m[1] = (w > 0.f) ? w : ((b.y > cut) ? (b.y + w) : NEG_INF);
            w = d.z + b.z; m[2] = (w > 0.f) ? w : ((b.z > cut) ? (b.z + w) : NEG_INF);
            w = d.w + b.w; m[3] = (w > 0.f) ? w : ((b.w > cut) ? (b.w + w) : NEG_INF);
        }
        *(float4*)&g_mask[(size_t)(ibase + r) * NN + j0] =
            make_float4(m[0], m[1], m[2], m[3]);
#pragma unroll
        for (int h = 0; h < HH; h++) {
            const float ssv = ss[h][r];
#pragma unroll
            for (int q = 0; q < 4; q++) {
                float x = ssv + st[h][q];
                x = fmaxf(x, 0.2f * x);
                acc[h][q] += ex2f(fmaf(m[q], LOG2E, x));
            }
        }
        d = nd; b = nb;
    }
#pragma unroll
    for (int h = 0; h < HH; h++)
        *(float4*)&g_part[((size_t)blockIdx.x * HH + h) * NN + j0] =
            make_float4(acc[h][0], acc[h][1], acc[h][2], acc[h][3]);
}

// ---------------- k2b: reduce 128 chunks -> -log2(denom) -------------------
__global__ void k2b_reduce() {
    const int id = blockIdx.x * 256 + threadIdx.x;   // h*NN + j
    float s0 = 0.f, s1 = 0.f, s2 = 0.f, s3 = 0.f;
#pragma unroll
    for (int c = 0; c < 128; c += 4) {
        s0 += g_part[(size_t)(c + 0) * HH * NN + id];
        s1 += g_part[(size_t)(c + 1) * HH * NN + id];
        s2 += g_part[(size_t)(c + 2) * HH * NN + id];
        s3 += g_part[(size_t)(c + 3) * HH * NN + id];
    }
    const float s = (s0 + s1) + (s2 + s3);
    const int h = id >> 12, j = id & (NN - 1);
    g_nld2[j >> 6][h][j & 63] = -__log2f(s);
}

// ---------------- k3: M=64 bf16 mma, register A-frags, mbar pipeline -------
struct K3Smem {
    __nv_bfloat16 p[2][HH][64][72];   // 73.7 KB
    float m[2][64][68];               // 34.8 KB
    float st[2][HH][64];              // x log2e
    float ld[2][HH][64];              // -log2(denom)
    float ss[HH][64];                 // x log2e
    unsigned long long dmb[2];
    unsigned long long cmb[2];
};
#define K3_TX_BYTES (64 * 256 + HH * 9216 + 1024 + 1024)   // 55296

__device__ __forceinline__ void k3_issue(K3Smem* S, int ibase, int jt, int buf,
                                         uint32_t mb) {
    mbar_expect_tx(mb, K3_TX_BYTES);
    const int jbase = jt * 64;
#pragma unroll 4
    for (int r = 0; r < 64; r++)
        bulkcp(&S->m[buf][r][0], &g_mask[(size_t)(ibase + r) * NN + jbase], 256, mb);
#pragma unroll
    for (int h2 = 0; h2 < HH; h2++)
        bulkcp(&S->p[buf][h2][0][0], &g_projp[h2][jt][0][0], 9216, mb);
    bulkcp(&S->st[buf][0][0], &g_stgt2[jt][0][0], 1024, mb);
    bulkcp(&S->ld[buf][0][0], &g_nld2[jt][0][0], 1024, mb);
}

__global__ void __launch_bounds__(256, 2) k3_mma(void) {
    extern __shared__ char smem_raw[];
    K3Smem* S = (K3Smem*)smem_raw;

    const int tid = threadIdx.x;
    const int ibase = blockIdx.x * 64;
    const int split = blockIdx.y;
    const int jt0 = split * 16;
    const int wp = tid >> 5;
    const int lane = tid & 31;
    const int h = wp >> 1;
    const int mh = (wp & 1) * 32;
    const int g = lane >> 2;
    const int t = lane & 3;
    const int rA0 = mh + g,      rA1 = rA0 + 8;
    const int rB0 = mh + 16 + g, rB1 = rB0 + 8;

    const uint32_t dmb0 = smem_u32(&S->dmb[0]);
    const uint32_t dmb1 = smem_u32(&S->dmb[1]);
    const uint32_t cmb0 = smem_u32(&S->cmb[0]);
    const uint32_t cmb1 = smem_u32(&S->cmb[1]);

    {
        const int h2 = tid >> 6, ii = tid & 63;
        S->ss[h2][ii] = g_ssrc[h2 * NN + ibase + ii] * LOG2E;
    }
    if (tid == 0) {
        mbar_init(dmb0, 1);
        mbar_init(dmb1, 1);
        mbar_init(cmb0, 8);
        mbar_init(cmb1, 8);
        asm volatile("fence.proxy.async.shared::cta;" ::: "memory");
    }
    __syncthreads();
    if (tid == 0) {
        k3_issue(S, ibase, jt0 + 0, 0, dmb0);
        k3_issue(S, ibase, jt0 + 1, 1, dmb1);
    }

    const float ssA0 = S->ss[h][rA0], ssA1 = S->ss[h][rA1];
    const float ssB0 = S->ss[h][rB0], ssB1 = S->ss[h][rB1];

    float acc0[8][4], acc1[8][4];
#pragma unroll
    for (int nt = 0; nt < 8; nt++)
#pragma unroll
        for (int q = 0; q < 4; q++) { acc0[nt][q] = 0.f; acc1[nt][q] = 0.f; }

    for (int jx = 0; jx < 16; jx++) {
        const int buf = jx & 1;
        mbar_wait(buf ? dmb1 : dmb0, (jx >> 1) & 1);

        const uint32_t p_base = smem_u32(&S->p[buf][h][lane & 15][(lane >> 4) * 8]);

#pragma unroll
        for (int ks = 0; ks < 4; ks++) {
            const int c = ks * 16 + 2 * t;
            const float2 stv  = *(const float2*)&S->st[buf][h][c];
            const float2 ldv  = *(const float2*)&S->ld[buf][h][c];
            const float2 stv2 = *(const float2*)&S->st[buf][h][c + 8];
            const float2 ldv2 = *(const float2*)&S->ld[buf][h][c + 8];

            uint32_t a0, a1, a2, a3, b0, b1, b2, b3;
            {
                float2 mm0 = *(const float2*)&S->m[buf][rA0][c];
                float2 mm1 = *(const float2*)&S->m[buf][rA1][c];
                float x00 = ssA0 + stv.x; x00 = fmaxf(x00, 0.2f * x00);
                float x01 = ssA0 + stv.y; x01 = fmaxf(x01, 0.2f * x01);
                float x10 = ssA1 + stv.x; x10 = fmaxf(x10, 0.2f * x10);
                float x11 = ssA1 + stv.y; x11 = fmaxf(x11, 0.2f * x11);
                a0 = packbf2(ex2f(fmaf(mm0.x, LOG2E, x00 + ldv.x)),
                             ex2f(fmaf(mm0.y, LOG2E, x01 + ldv.y)));
                a1 = packbf2(ex2f(fmaf(mm1.x, LOG2E, x10 + ldv.x)),
                             ex2f(fmaf(mm1.y, LOG2E, x11 + ldv.y)));
                mm0 = *(const float2*)&S->m[buf][rA0][c + 8];
                mm1 = *(const float2*)&S->m[buf][rA1][c + 8];
                x00 = ssA0 + stv2.x; x00 = fmaxf(x00, 0.2f * x00);
                x01 = ssA0 + stv2.y; x01 = fmaxf(x01, 0.2f * x01);
                x10 = ssA1 + stv2.x; x10 = fmaxf(x10, 0.2f * x10);
                x11 = ssA1 + stv2.y; x11 = fmaxf(x11, 0.2f * x11);
                a2 = packbf2(ex2f(fmaf(mm0.x, LOG2E, x00 + ldv2.x)),
                             ex2f(fmaf(mm0.y, LOG2E, x01 + ldv2.y)));
                a3 = packbf2(ex2f(fmaf(mm1.x, LOG2E, x10 + ldv2.x)),
                             ex2f(fmaf(mm1.y, LOG2E, x11 + ldv2.y)));
            }
            {
                float2 mm0 = *(const float2*)&S->m[buf][rB0][c];
                float2 mm1 = *(const float2*)&S->m[buf][rB1][c];
                float x00 = ssB0 + stv.x; x00 = fmaxf(x00, 0.2f * x00);
                float x01 = ssB0 + stv.y; x01 = fmaxf(x01, 0.2f * x01);
                float x10 = ssB1 + stv.x; x10 = fmaxf(x10, 0.2f * x10);
                float x11 = ssB1 + stv.y; x11 = fmaxf(x11, 0.2f * x11);
                b0 = packbf2(ex2f(fmaf(mm0.x, LOG2E, x00 + ldv.x)),
                             ex2f(fmaf(mm0.y, LOG2E, x01 + ldv.y)));
                b1 = packbf2(ex2f(fmaf(mm1.x, LOG2E, x10 + ldv.x)),
                             ex2f(fmaf(mm1.y, LOG2E, x11 + ldv.y)));
                mm0 = *(const float2*)&S->m[buf][rB0][c + 8];
                mm1 = *(const float2*)&S->m[buf][rB1][c + 8];
                x00 = ssB0 + stv2.x; x00 = fmaxf(x00, 0.2f * x00);
                x01 = ssB0 + stv2.y; x01 = fmaxf(x01, 0.2f * x01);
                x10 = ssB1 + stv2.x; x10 = fmaxf(x10, 0.2f * x10);
                x11 = ssB1 + stv2.y; x11 = fmaxf(x11, 0.2f * x11);
                b2 = packbf2(ex2f(fmaf(mm0.x, LOG2E, x00 + ldv2.x)),
                             ex2f(fmaf(mm0.y, LOG2E, x01 + ldv2.y)));
                b3 = packbf2(ex2f(fmaf(mm1.x, LOG2E, x10 + ldv2.x)),
                             ex2f(fmaf(mm1.y, LOG2E, x11 + ldv2.y)));
            }
#pragma unroll
            for (int nb = 0; nb < 4; nb++) {
                uint32_t B0, B1, B2, B3;
                LDSM_X4T(B0, B1, B2, B3, p_base + ks * 16 * 144 + nb * 32);
                mma_bf16(acc0[2 * nb],     a0, a1, a2, a3, B0, B1);
                mma_bf16(acc0[2 * nb + 1], a0, a1, a2, a3, B2, B3);
                mma_bf16(acc1[2 * nb],     b0, b1, b2, b3, B0, B1);
                mma_bf16(acc1[2 * nb + 1], b0, b1, b2, b3, B2, B3);
            }
        }

        if (lane == 0) mbar_arrive(buf ? cmb1 : cmb0);
        if (tid == 0 && jx + 2 < 16) {
            mbar_wait(buf ? cmb1 : cmb0, (jx >> 1) & 1);
            k3_issue(S, ibase, jt0 + jx + 2, buf, buf ? dmb1 : dmb0);
        }
    }

    float* po = g_pout[split];
#pragma unroll
    for (int nt = 0; nt < 8; nt++) {
        const int f0 = nt * 8 + t * 2;
#pragma unroll
        for (int q = 0; q < 4; q++) {
            const int f = f0 + (q & 1);
            const int nA = ibase + ((q >= 2) ? rA1 : rA0);
            const int nB = ibase + ((q >= 2) ? rB1 : rB0);
            po[nA * (HH * F_OUT) + h * F_OUT + f] = acc0[nt][q];
            po[nB * (HH * F_OUT) + h * F_OUT + f] = acc1[nt][q];
        }
    }
}

// ---------------- k1b: row LayerNorm from mask -----------------------------
__global__ void k1b_ln(float* __restrict__ ln_out) {
    const int i = blockIdx.x;
    const int tid = threadIdx.x;
    const size_t row = (size_t)i * NN;

    float4 m4[2];
    float s = 0.f, s2 = 0.f;
#pragma unroll
    for (int k = 0; k < 2; k++) {
        const int j4 = (k * 512 + tid) * 4;
        const float4 m = __ldcs((const float4*)&g_mask[row + j4]);
        m4[k] = m;
        s  += (m.x + m.y) + (m.z + m.w);
        s2 += (m.x * m.x + m.y * m.y) + (m.z * m.z + m.w * m.w);
    }
    __shared__ float rs[16], rs2[16];
    const int lane = tid & 31, wp = tid >> 5;
#pragma unroll
    for (int off = 16; off; off >>= 1) {
        s  += __shfl_down_sync(0xffffffffu, s, off);
        s2 += __shfl_down_sync(0xffffffffu, s2, off);
    }
    if (lane == 0) { rs[wp] = s; rs2[wp] = s2; }
    __syncthreads();
    if (wp == 0) {
        float a  = (lane < 16) ? rs[lane] : 0.f;
        float a2 = (lane < 16) ? rs2[lane] : 0.f;
#pragma unroll
        for (int off = 8; off; off >>= 1) {
            a  += __shfl_down_sync(0xffffffffu, a, off);
            a2 += __shfl_down_sync(0xffffffffu, a2, off);
        }
        if (lane == 0) { rs[0] = a; rs2[0] = a2; }
    }
    __syncthreads();
    const float mu  = rs[0] * (1.0f / NN);
    const float var = fmaxf(rs2[0] * (1.0f / NN) - mu * mu, 0.f);
    const float rstd = 1.0f / sqrtf(var + LN_EPS);
#pragma unroll
    for (int k = 0; k < 2; k++) {
        const int j4 = (k * 512 + tid) * 4;
        float4 o4;
        o4.x = (m4[k].x - mu) * rstd;
        o4.y = (m4[k].y - mu) * rstd;
        o4.z = (m4[k].z - mu) * rstd;
        o4.w = (m4[k].w - mu) * rstd;
        __stcs((float4*)&ln_out[row + j4], o4);
    }
}

// ---------------- k4: combine 4 splits + skip + ELU ------------------------
__global__ void k4_combine(float* __restrict__ out) {
    const int i4 = (blockIdx.x * 256 + threadIdx.x) * 4;
    const float4 p0 = *(const float4*)&g_pout[0][i4];
    const float4 p1 = *(const float4*)&g_pout[1][i4];
    const float4 p2 = *(const float4*)&g_pout[2][i4];
    const float4 p3 = *(const float4*)&g_pout[3][i4];
    const float4 sk = *(const float4*)&g_skip[i4];
    float4 o;
    float v;
    v = (p0.x + p1.x) + (p2.x + p3.x) + sk.x; o.x = (v > 0.f) ? v : (__expf(v) - 1.f);
    v = (p0.y + p1.y) + (p2.y + p3.y) + sk.y; o.y = (v > 0.f) ? v : (__expf(v) - 1.f);
    v = (p0.z + p1.z) + (p2.z + p3.z) + sk.z; o.z = (v > 0.f) ? v : (__expf(v) - 1.f);
    v = (p0.w + p1.w) + (p2.w + p3.w) + sk.w; o.w = (v > 0.f) ? v : (__expf(v) - 1.f);
    *(float4*)&out[i4] = o;
}

// ---------------- launch ---------------------------------------------------
extern "C" void kernel_launch(void* const* d_in, const int* in_sizes, int n_in,
                              void* d_out, int out_size) {
    const float* nodes = (const float*)d_in[0];
    const float* deg   = (const float*)d_in[1];
    const float* bond  = (const float*)d_in[3];
    const float* pp    = (const float*)d_in[4];
    const float* wsrc  = (const float*)d_in[5];
    const float* wtgt  = (const float*)d_in[6];
    const float* skw   = (const float*)d_in[7];
    const int*   cut   = (const int*)d_in[8];

    float* out    = (float*)d_out;
    float* ln_out = (float*)d_out + (size_t)NN * HH * F_OUT;

    const int k3_smem = (int)sizeof(K3Smem);
    cudaFuncSetAttribute(k3_mma, cudaFuncAttributeMaxDynamicSharedMemorySize, k3_smem);

    k0_fused<<<256, 256>>>(nodes, pp, skw, wsrc, wtgt);
    kA_mask_colsum<<<dim3(128, 2), 512>>>(deg, bond, cut);
    k2b_reduce<<<64, 256>>>();
    k3_mma<<<dim3(64, 4), 256, k3_smem>>>();      // 4th launch -> profiled
    k1b_ln<<<NN, 512>>>(ln_out);
    k4_combine<<<1024, 256>>>(out);
}